// round 1
// baseline (speedup 1.0000x reference)
#include <cuda_runtime.h>
#include <cstdint>

#define NN 4096
#define FF 32
#define HF 64
#define CC 10
#define GG 13
#define EE 65536
#define ETOT (EE + NN)   // 69632

// ---------------- scratch (static __device__, no allocation) ----------------
static __device__ float g_af[NN * FF];                    // |x|
static __device__ float g_g1[4 * NN * FF];                // [U;psi] @ af
static __device__ float g_a1[NN * 96];                    // |y1| repacked [n][j*32+f]
static __device__ float g_g2[4 * NN * 96];                // [U;psi] @ a1
static __device__ float g_b3[NN * 288];                   // |y2| repacked [n][(j*3+k)*32+f]
static __device__ float g_g3[NN * 288];                   // U @ b3
static __device__ float g_coefs[GG * NN * FF];            // 13 coefficient maps
static __device__ float g_h[(size_t)GG * NN * HF];        // GAT h per branch
static __device__ float g_es[GG * NN * 2];
static __device__ float g_ed[GG * NN * 2];
static __device__ float g_feat[(size_t)NN * GG * HF];     // concat branch MLP outputs
static __device__ int   g_off[NN + 1];
static __device__ int   g_cur[NN];
static __device__ int   g_csrc[ETOT];

// ---------------- small elementwise / repack kernels ----------------
__global__ void k_abs(const float* __restrict__ x) {
    int i = blockIdx.x * 256 + threadIdx.x;
    g_af[i] = fabsf(x[i]);
}

__global__ void k_a1() {
    int i = blockIdx.x * 256 + threadIdx.x;          // NN*96
    int n = i / 96, c = i - (i / 96) * 96;
    int j = c >> 5, f = c & 31;
    g_a1[i] = fabsf(g_g1[((size_t)(1 + j) * NN + n) * FF + f]);
}

__global__ void k_b3() {
    int i = blockIdx.x * 256 + threadIdx.x;          // NN*288
    int n = i / 288, c = i - (i / 288) * 288;
    int idx = c >> 5, f = c & 31;
    int j = idx / 3, k = idx - 3 * (idx / 3);
    g_b3[i] = fabsf(g_g2[((size_t)(1 + k) * NN + n) * 96 + j * 32 + f]);
}

__global__ void k_coefs() {
    int i = blockIdx.x * 256 + threadIdx.x;          // GG*NN*FF
    int g = i / (NN * FF);
    int r = i - g * (NN * FF);
    int n = r >> 5, f = r & 31;
    float v;
    if (g == 0)      v = g_g1[(size_t)n * FF + f];
    else if (g < 4)  v = g_g2[(size_t)n * 96 + (g - 1) * 32 + f];
    else             v = g_g3[(size_t)n * 288 + (g - 4) * 32 + f];
    g_coefs[i] = v;
}

// ---------------- CSR build (by dst, with self loops) ----------------
__global__ void k_csr_init() {
    int i = blockIdx.x * 256 + threadIdx.x;
    if (i < NN) g_cur[i] = 1;                         // self loop per node
}

__global__ void k_csr_hist(const int* __restrict__ ei) {
    int i = blockIdx.x * 256 + threadIdx.x;           // EE exact
    atomicAdd(&g_cur[ei[EE + i]], 1);
}

__global__ void __launch_bounds__(1024) k_csr_scan() {
    int t = threadIdx.x;                              // 1024 threads, 4 elems each
    int b = t * 4;
    int c0 = g_cur[b], c1 = g_cur[b + 1], c2 = g_cur[b + 2], c3 = g_cur[b + 3];
    int s1 = c0 + c1, s2 = s1 + c2, tot = s2 + c3;
    int lane = t & 31, wid = t >> 5;
    int x = tot;
    #pragma unroll
    for (int o = 1; o < 32; o <<= 1) {
        int y = __shfl_up_sync(0xffffffffu, x, o);
        if (lane >= o) x += y;
    }
    __shared__ int ws[32];
    if (lane == 31) ws[wid] = x;
    __syncthreads();
    if (wid == 0) {
        int y = ws[lane];
        #pragma unroll
        for (int o = 1; o < 32; o <<= 1) {
            int z = __shfl_up_sync(0xffffffffu, y, o);
            if (lane >= o) y += z;
        }
        ws[lane] = y;
    }
    __syncthreads();
    int excl = x - tot + (wid ? ws[wid - 1] : 0);
    g_off[b] = excl; g_off[b + 1] = excl + c0; g_off[b + 2] = excl + s1; g_off[b + 3] = excl + s2;
    g_cur[b] = excl; g_cur[b + 1] = excl + c0; g_cur[b + 2] = excl + s1; g_cur[b + 3] = excl + s2;
    if (t == 1023) g_off[NN] = excl + tot;
}

__global__ void k_csr_scatter(const int* __restrict__ ei) {
    int i = blockIdx.x * 256 + threadIdx.x;           // ETOT exact
    int s, d;
    if (i < EE) { s = ei[i]; d = ei[EE + i]; }
    else        { s = d = i - EE; }
    int pos = atomicAdd(&g_cur[d], 1);
    g_csrc[pos] = s;
}

// ---------------- f32x2 SIMT GEMM: C = [U(;psi)] @ B ----------------
__device__ __forceinline__ const float* selB(int s) {
    return s == 0 ? g_af : (s == 1 ? g_a1 : g_b3);
}
__device__ __forceinline__ float* selC(int s) {
    return s == 0 ? g_g1 : (s == 1 ? g_g2 : g_g3);
}

template<int BN, int TN>
__global__ void __launch_bounds__(256)
k_gemm(const float* __restrict__ U, const float* __restrict__ psi,
       int usepsi, int sel, int ldb, int ldc)
{
    constexpr int BM = 128, BK = 32, TM = 8;
    __shared__ float As[BM][BK + 1];
    __shared__ float Bs[BK][BN];
    const float* __restrict__ B = selB(sel);
    float* __restrict__ C = selC(sel);
    const int K = 4096;
    int tid = threadIdx.x;
    int row0 = blockIdx.x * BM;
    const float* A = (usepsi && row0 >= NN) ? (psi + (size_t)(row0 - NN) * K)
                                            : (U + (size_t)row0 * K);
    int col0 = blockIdx.y * BN;
    int tx = tid & 15, ty = tid >> 4;
    int ar = tid >> 3;                // 0..31
    int ak = (tid & 7) << 2;          // 0,4,...,28

    unsigned long long acc[TM][TN / 2];
    #pragma unroll
    for (int i = 0; i < TM; i++)
        #pragma unroll
        for (int j = 0; j < TN / 2; j++) acc[i][j] = 0ull;

    for (int kt = 0; kt < K; kt += BK) {
        #pragma unroll
        for (int r = 0; r < 4; r++) {
            const float4 v = *reinterpret_cast<const float4*>(
                A + (size_t)(ar + r * 32) * K + kt + ak);
            As[ar + r * 32][ak + 0] = v.x;
            As[ar + r * 32][ak + 1] = v.y;
            As[ar + r * 32][ak + 2] = v.z;
            As[ar + r * 32][ak + 3] = v.w;
        }
        #pragma unroll
        for (int i = 0; i < (BK * BN) / 256; i++) {
            int idx = tid + i * 256;
            int br = idx / BN, bc = idx - br * BN;
            Bs[br][bc] = B[(size_t)(kt + br) * ldb + col0 + bc];
        }
        __syncthreads();
        #pragma unroll
        for (int k = 0; k < BK; k++) {
            unsigned long long ad[TM];
            #pragma unroll
            for (int i = 0; i < TM; i++) {
                float av = As[ty * TM + i][k];
                asm("mov.b64 %0, {%1, %1};" : "=l"(ad[i]) : "f"(av));
            }
            unsigned long long bv[TN / 2];
            #pragma unroll
            for (int j = 0; j < TN / 2; j++)
                bv[j] = *reinterpret_cast<const unsigned long long*>(
                            &Bs[k][tx * TN + 2 * j]);
            #pragma unroll
            for (int i = 0; i < TM; i++)
                #pragma unroll
                for (int j = 0; j < TN / 2; j++)
                    asm("fma.rn.f32x2 %0, %1, %2, %0;"
                        : "+l"(acc[i][j]) : "l"(ad[i]), "l"(bv[j]));
        }
        __syncthreads();
    }
    #pragma unroll
    for (int i = 0; i < TM; i++) {
        size_t r = row0 + ty * TM + i;
        #pragma unroll
        for (int j = 0; j < TN / 2; j++) {
            float lo, hi;
            asm("mov.b64 {%0, %1}, %2;" : "=f"(lo), "=f"(hi) : "l"(acc[i][j]));
            C[r * ldc + col0 + tx * TN + 2 * j]     = lo;
            C[r * ldc + col0 + tx * TN + 2 * j + 1] = hi;
        }
    }
}

// ---------------- GAT: h, es, ed per branch ----------------
__global__ void __launch_bounds__(64)
k_h(const float* __restrict__ gat_W, const float* __restrict__ att_src,
    const float* __restrict__ att_dst)
{
    int g = blockIdx.y;
    int j = threadIdx.x;                               // 0..63 = head*32+f
    float w[32];
    #pragma unroll
    for (int k = 0; k < 32; k++) w[k] = gat_W[((size_t)g * 32 + k) * 64 + j];
    float as = att_src[g * 64 + j];
    float ad = att_dst[g * 64 + j];
    __shared__ float cof[32];
    for (int t = 0; t < 16; t++) {
        int n = blockIdx.x * 16 + t;
        if (j < 32) cof[j] = g_coefs[((size_t)g * NN + n) * FF + j];
        __syncthreads();
        float acc = 0.f;
        #pragma unroll
        for (int k = 0; k < 32; k++) acc += w[k] * cof[k];
        g_h[((size_t)g * NN + n) * HF + j] = acc;
        float vs = acc * as, vd = acc * ad;
        #pragma unroll
        for (int o = 16; o; o >>= 1) {
            vs += __shfl_xor_sync(0xffffffffu, vs, o);
            vd += __shfl_xor_sync(0xffffffffu, vd, o);
        }
        if ((j & 31) == 0) {
            g_es[((size_t)g * NN + n) * 2 + (j >> 5)] = vs;
            g_ed[((size_t)g * NN + n) * 2 + (j >> 5)] = vd;
        }
        __syncthreads();
    }
}

// ---------------- GAT aggregation + branch MLP (one block per node,branch) ----
__global__ void __launch_bounds__(64)
k_agg(const float* __restrict__ gat_b, const float* __restrict__ mlp_W,
      const float* __restrict__ mlp_b)
{
    int n = blockIdx.x, g = blockIdx.y;
    int tid = threadIdx.x;
    int lane = tid & 31;
    int head = tid >> 5;
    int beg = g_off[n];
    int deg = g_off[n + 1] - beg;
    float2 edn = *reinterpret_cast<const float2*>(&g_ed[((size_t)g * NN + n) * 2]);

    // pass 1: per-head segment max (leaky relu logits)
    float m0 = -1e30f, m1 = -1e30f;
    for (int i = tid; i < deg; i += 64) {
        int s = g_csrc[beg + i];
        float2 e = *reinterpret_cast<const float2*>(&g_es[((size_t)g * NN + s) * 2]);
        float e0 = e.x + edn.x; e0 = e0 > 0.f ? e0 : 0.2f * e0;
        float e1 = e.y + edn.y; e1 = e1 > 0.f ? e1 : 0.2f * e1;
        m0 = fmaxf(m0, e0); m1 = fmaxf(m1, e1);
    }
    #pragma unroll
    for (int o = 16; o; o >>= 1) {
        m0 = fmaxf(m0, __shfl_xor_sync(0xffffffffu, m0, o));
        m1 = fmaxf(m1, __shfl_xor_sync(0xffffffffu, m1, o));
    }
    __shared__ float pm0[2], pm1[2];
    if (lane == 0) { pm0[head] = m0; pm1[head] = m1; }
    __syncthreads();
    m0 = fmaxf(pm0[0], pm0[1]);
    m1 = fmaxf(pm1[0], pm1[1]);

    // pass 2+3 fused: chunk 32 edges, warp0 computes w, all 64 accumulate w*h
    __shared__ float wbuf[2][32];
    __shared__ int   sbuf[32];
    float acc = 0.f, zp0 = 0.f, zp1 = 0.f;
    const float* hb = &g_h[(size_t)g * NN * HF];
    for (int c = 0; c < deg; c += 32) {
        __syncthreads();
        if (tid < 32) {
            int i = c + lane;
            float w0 = 0.f, w1 = 0.f; int s = 0;
            if (i < deg) {
                s = g_csrc[beg + i];
                float2 e = *reinterpret_cast<const float2*>(&g_es[((size_t)g * NN + s) * 2]);
                float e0 = e.x + edn.x; e0 = e0 > 0.f ? e0 : 0.2f * e0;
                float e1 = e.y + edn.y; e1 = e1 > 0.f ? e1 : 0.2f * e1;
                w0 = expf(e0 - m0); w1 = expf(e1 - m1);
            }
            wbuf[0][lane] = w0; wbuf[1][lane] = w1; sbuf[lane] = s;
            zp0 += w0; zp1 += w1;
        }
        __syncthreads();
        int lim = min(32, deg - c);
        for (int i = 0; i < lim; i++)
            acc += wbuf[head][i] * hb[(size_t)sbuf[i] * HF + tid];
    }
    __shared__ float sz[2];
    if (tid < 32) {
        #pragma unroll
        for (int o = 16; o; o >>= 1) {
            zp0 += __shfl_xor_sync(0xffffffffu, zp0, o);
            zp1 += __shfl_xor_sync(0xffffffffu, zp1, o);
        }
        if (lane == 0) { sz[0] = zp0; sz[1] = zp1; }
    }
    __syncthreads();
    float v = acc / (sz[head] + 1e-16f) + gat_b[g * HF + tid];
    v = v > 0.f ? v : expm1f(v);                      // ELU
    __shared__ float sh[64];
    sh[tid] = v;
    __syncthreads();
    float o = mlp_b[g * HF + tid];
    const float* mw = mlp_W + (size_t)g * HF * HF + tid;
    #pragma unroll 8
    for (int k = 0; k < 64; k++) o += sh[k] * mw[k * 64];
    g_feat[(size_t)n * (GG * HF) + g * HF + tid] = o;
}

// ---------------- final head + log_softmax (one warp per node) ----------------
__global__ void __launch_bounds__(128)
k_out(const float* __restrict__ out_W, const float* __restrict__ out_b,
      float* __restrict__ out)
{
    int node = blockIdx.x * 4 + (threadIdx.x >> 5);
    int lane = threadIdx.x & 31;
    float acc[CC];
    #pragma unroll
    for (int c = 0; c < CC; c++) acc[c] = 0.f;
    const float* fr = &g_feat[(size_t)node * (GG * HF)];
    for (int k = lane; k < GG * HF; k += 32) {
        float v = fr[k];
        v = v > 0.f ? v : expm1f(v);                  // ELU
        #pragma unroll
        for (int c = 0; c < CC; c++) acc[c] += v * out_W[k * CC + c];
    }
    #pragma unroll
    for (int c = 0; c < CC; c++) {
        #pragma unroll
        for (int o = 16; o; o >>= 1)
            acc[c] += __shfl_xor_sync(0xffffffffu, acc[c], o);
        acc[c] += out_b[c];
    }
    float m = acc[0];
    #pragma unroll
    for (int c = 1; c < CC; c++) m = fmaxf(m, acc[c]);
    float s = 0.f;
    #pragma unroll
    for (int c = 0; c < CC; c++) s += expf(acc[c] - m);
    float lse = m + logf(s);
    if (lane < CC) out[(size_t)node * CC + lane] = acc[lane] - lse;
}

// ---------------- launcher ----------------
extern "C" void kernel_launch(void* const* d_in, const int* in_sizes, int n_in,
                              void* d_out, int out_size)
{
    const float* x       = (const float*)d_in[0];
    const int*   ei      = (const int*)  d_in[1];
    const float* U       = (const float*)d_in[2];
    const float* psi     = (const float*)d_in[3];
    const float* gat_W   = (const float*)d_in[4];
    const float* att_src = (const float*)d_in[5];
    const float* att_dst = (const float*)d_in[6];
    const float* gat_b   = (const float*)d_in[7];
    const float* mlp_W   = (const float*)d_in[8];
    const float* mlp_b   = (const float*)d_in[9];
    const float* out_W   = (const float*)d_in[10];
    const float* out_b   = (const float*)d_in[11];
    float* out = (float*)d_out;

    // CSR build (independent of GEMM chain)
    k_csr_init<<<16, 256>>>();
    k_csr_hist<<<EE / 256, 256>>>(ei);
    k_csr_scan<<<1, 1024>>>();
    k_csr_scatter<<<ETOT / 256, 256>>>(ei);

    // scattering-tree GEMM chain
    k_abs<<<(NN * FF) / 256, 256>>>(x);
    k_gemm<32, 2><<<dim3(128, 1), 256>>>(U, psi, 1, 0, 32, 32);     // [U;psi]@af
    k_a1<<<(NN * 96) / 256, 256>>>();
    k_gemm<96, 6><<<dim3(128, 1), 256>>>(U, psi, 1, 1, 96, 96);     // [U;psi]@|y1|
    k_b3<<<(NN * 288) / 256, 256>>>();
    k_gemm<96, 6><<<dim3(32, 3), 256>>>(U, psi, 0, 2, 288, 288);    // U@|y2|
    k_coefs<<<(GG * NN * FF) / 256, 256>>>();

    // GAT branches + MLPs
    k_h<<<dim3(NN / 16, GG), 64>>>(gat_W, att_src, att_dst);
    k_agg<<<dim3(NN, GG), 64>>>(gat_b, mlp_W, mlp_b);

    // final head + log_softmax
    k_out<<<NN / 4, 128>>>(out_W, out_b, out);
}

// round 3
// speedup vs baseline: 2.2200x; 2.2200x over previous
#include <cuda_runtime.h>
#include <cuda_bf16.h>
#include <cstdint>

#define NN 4096
#define FF 32
#define HF 64
#define CC 10
#define GG 13
#define EE 65536
#define ETOT (EE + NN)   // 69632

// ---------------- scratch (static __device__, no allocation) ----------------
static __device__ __align__(16) float g_g1[4 * NN * FF];     // [U;psi] @ af   [16384][32]
static __device__ __align__(16) float g_g2[4 * NN * 96];     // [U;psi] @ a1   [16384][96]
static __device__ __align__(16) float g_g3[NN * 288];        // U @ b3         [4096][288]
static __device__ float g_coefs[GG * NN * FF];               // 13 coefficient maps
static __device__ __align__(16) __nv_bfloat16 g_afh[32 * NN],  g_afl[32 * NN];   // |x|^T split
static __device__ __align__(16) __nv_bfloat16 g_a1h[96 * NN],  g_a1l[96 * NN];   // |y1|^T split
static __device__ __align__(16) __nv_bfloat16 g_b3h[288 * NN], g_b3l[288 * NN];  // |y2|^T split
static __device__ float g_h[(size_t)GG * NN * HF];           // GAT h per branch
static __device__ float g_es[GG * NN * 2];
static __device__ float g_ed[GG * NN * 2];
static __device__ float g_feat[(size_t)NN * GG * HF];        // concat branch MLP outputs
static __device__ int   g_off[NN + 1];
static __device__ int   g_cur[NN];
static __device__ int   g_csrc[ETOT];

// ---------------- helpers ----------------
__device__ __forceinline__ void bf16split(float v, __nv_bfloat16& h, __nv_bfloat16& l) {
    h = __float2bfloat16_rn(v);
    l = __float2bfloat16_rn(v - __bfloat162float(h));
}
__device__ __forceinline__ uint32_t pk(__nv_bfloat16 a, __nv_bfloat16 b) {
    __nv_bfloat162 t = __halves2bfloat162(a, b);
    return *reinterpret_cast<uint32_t*>(&t);
}
__device__ __forceinline__ uint32_t s2u(const void* p) {
    uint32_t a;
    asm("{ .reg .u64 t; cvta.to.shared.u64 t, %1; cvt.u32.u64 %0, t; }" : "=r"(a) : "l"(p));
    return a;
}

#define CP_ASYNC16(saddr, gaddr) \
    asm volatile("cp.async.cg.shared.global [%0], [%1], 16;" :: "r"(saddr), "l"(gaddr))
#define CP_COMMIT() asm volatile("cp.async.commit_group;" ::: "memory")
#define CP_WAIT1()  asm volatile("cp.async.wait_group 1;" ::: "memory")
#define CP_WAIT0()  asm volatile("cp.async.wait_group 0;" ::: "memory")

#define LDMX4(r0, r1, r2, r3, a) \
    asm volatile("ldmatrix.sync.aligned.m8n8.x4.shared.b16 {%0,%1,%2,%3}, [%4];" \
                 : "=r"(r0), "=r"(r1), "=r"(r2), "=r"(r3) : "r"(a))
#define LDMX2(r0, r1, a) \
    asm volatile("ldmatrix.sync.aligned.m8n8.x2.shared.b16 {%0,%1}, [%2];" \
                 : "=r"(r0), "=r"(r1) : "r"(a))
#define MMA16816(c, a0, a1, a2, a3, b0, b1) \
    asm volatile("mma.sync.aligned.m16n8k16.row.col.f32.bf16.bf16.f32 " \
                 "{%0,%1,%2,%3}, {%4,%5,%6,%7}, {%8,%9}, {%0,%1,%2,%3};" \
                 : "+f"((c)[0]), "+f"((c)[1]), "+f"((c)[2]), "+f"((c)[3]) \
                 : "r"(a0), "r"(a1), "r"(a2), "r"(a3), "r"(b0), "r"(b1))

// ---------------- transpose + abs + bf16-split repack kernels ----------------
__global__ void k_absT(const float* __restrict__ x) {
    __shared__ float s[32][33];
    int n0 = blockIdx.x * 32;
    int tx = threadIdx.x, ty = threadIdx.y;
    #pragma unroll
    for (int i = 0; i < 4; i++)
        s[ty + 8 * i][tx] = fabsf(x[(size_t)(n0 + ty + 8 * i) * 32 + tx]);
    __syncthreads();
    #pragma unroll
    for (int i = 0; i < 4; i++) {
        int f = ty + 8 * i;
        __nv_bfloat16 h, l; bf16split(s[tx][f], h, l);
        g_afh[(size_t)f * NN + n0 + tx] = h;
        g_afl[(size_t)f * NN + n0 + tx] = l;
    }
}

__global__ void k_a1T() {
    __shared__ float s[32][33];
    int n0 = blockIdx.x * 32, j = blockIdx.y;
    int tx = threadIdx.x, ty = threadIdx.y;
    #pragma unroll
    for (int i = 0; i < 4; i++)
        s[ty + 8 * i][tx] = fabsf(g_g1[((size_t)(1 + j) * NN + n0 + ty + 8 * i) * 32 + tx]);
    __syncthreads();
    #pragma unroll
    for (int i = 0; i < 4; i++) {
        int f = ty + 8 * i;
        __nv_bfloat16 h, l; bf16split(s[tx][f], h, l);
        g_a1h[(size_t)(j * 32 + f) * NN + n0 + tx] = h;
        g_a1l[(size_t)(j * 32 + f) * NN + n0 + tx] = l;
    }
}

__global__ void k_b3T() {
    __shared__ float s[32][33];
    int n0 = blockIdx.x * 32, y = blockIdx.y;          // y = j*3 + k
    int j = y / 3, k = y - 3 * j;
    int tx = threadIdx.x, ty = threadIdx.y;
    #pragma unroll
    for (int i = 0; i < 4; i++)
        s[ty + 8 * i][tx] = fabsf(g_g2[((size_t)(1 + k) * NN + n0 + ty + 8 * i) * 96 + j * 32 + tx]);
    __syncthreads();
    #pragma unroll
    for (int i = 0; i < 4; i++) {
        int f = ty + 8 * i;
        __nv_bfloat16 h, l; bf16split(s[tx][f], h, l);
        g_b3h[(size_t)(y * 32 + f) * NN + n0 + tx] = h;
        g_b3l[(size_t)(y * 32 + f) * NN + n0 + tx] = l;
    }
}

__global__ void k_coefs() {
    int i = blockIdx.x * 256 + threadIdx.x;            // GG*NN*FF
    int g = i / (NN * FF);
    int r = i - g * (NN * FF);
    int n = r >> 5, f = r & 31;
    float v;
    if (g == 0)      v = g_g1[(size_t)n * FF + f];
    else if (g < 4)  v = g_g2[(size_t)n * 96 + (g - 1) * 32 + f];
    else             v = g_g3[(size_t)n * 288 + (g - 4) * 32 + f];
    g_coefs[i] = v;
}

// ---------------- mma.sync 3xBF16 GEMM: C = [U(;psi)] @ B ----------------
// Block tile 128 x BN, K stage 64, 2-stage double buffer. 8 warps, warp = 16 rows.
// A fp32 loaded+split in-kernel; B hi/lo bf16 [col][node] copied via cp.async.
template<int BN>
__global__ void __launch_bounds__(256)
k_gemm_mma(const float* __restrict__ U, const float* __restrict__ psi,
           int usepsi, int sel, int ldc)
{
    extern __shared__ __align__(16) char sm[];
    constexpr int AP  = 144;                 // padded row pitch (72 bf16) -> conflict-free ldmatrix
    constexpr int ASZ = 128 * AP;            // one A operand (hi or lo)
    constexpr int BSZ = BN * AP;
    constexpr int STG = 2 * ASZ + 2 * BSZ;   // Ahi | Alo | Bhi | Blo
    constexpr int NT  = BN / 8;              // n-tiles per warp
    constexpr int BCH = BN * 8;              // 16B chunks per B operand per stage

    const int tid = threadIdx.x;
    const int warp = tid >> 5, lane = tid & 31;
    const int K = 4096;
    const int row0 = blockIdx.x * 128;
    const int col0 = blockIdx.y * BN;
    const float* __restrict__ A = (usepsi && row0 >= NN) ? psi + (size_t)(row0 - NN) * K
                                                         : U + (size_t)row0 * K;
    const __nv_bfloat16 *Bh, *Bl;
    float* C;
    if (sel == 0)      { Bh = g_afh; Bl = g_afl; C = g_g1; }
    else if (sel == 1) { Bh = g_a1h; Bl = g_a1l; C = g_g2; }
    else               { Bh = g_b3h; Bl = g_b3l; C = g_g3; }

    float c[NT][4];
    #pragma unroll
    for (int j = 0; j < NT; j++)
        #pragma unroll
        for (int q = 0; q < 4; q++) c[j][q] = 0.f;

    // A gmem/sts mapping: 8 x float4 per thread over the 128x64 fp32 tile
    const int ar_r[1] = {0};
    (void)ar_r;
    float4 areg[8];
    #pragma unroll
    for (int i = 0; i < 8; i++) {
        int p = tid * 4 + i * 1024;
        int r = p >> 6, cc = p & 63;
        areg[i] = *reinterpret_cast<const float4*>(A + (size_t)r * K + cc);
    }
    // B cp.async for stage 0
    {
        uint32_t sb = s2u(sm) + 2 * ASZ;
        #pragma unroll
        for (int i = 0; i < (2 * BCH) / 256; i++) {
            int q = tid + i * 256;
            int half = q >= BCH;                 // 0 = hi, 1 = lo
            int qq = q - half * BCH;
            int n = qq >> 3, c16 = qq & 7;
            const __nv_bfloat16* src = (half ? Bl : Bh) + (size_t)(col0 + n) * 4096 + c16 * 8;
            CP_ASYNC16(sb + half * BSZ + n * AP + c16 * 16, src);
        }
        CP_COMMIT();
    }

    // ldmatrix lane addressing (within-stage offsets)
    const int a_row = warp * 16 + (lane & 7) + ((lane >> 3) & 1) * 8;
    const int a_coff = (lane >> 4) * 16;               // k 0-7 vs 8-15 (bytes)
    const int b_row = lane & 7;
    const int b_coff = ((lane >> 3) & 1) * 16;

    for (int it = 0; it < 64; ++it) {
        char* buf = sm + (it & 1) * STG;
        // STS: split A regs into bf16 hi/lo
        #pragma unroll
        for (int i = 0; i < 8; i++) {
            int p = tid * 4 + i * 1024;
            int r = p >> 6, cc = p & 63;
            __nv_bfloat16 h0, h1, h2, h3, l0, l1, l2, l3;
            bf16split(areg[i].x, h0, l0); bf16split(areg[i].y, h1, l1);
            bf16split(areg[i].z, h2, l2); bf16split(areg[i].w, h3, l3);
            *reinterpret_cast<uint2*>(buf + r * AP + cc * 2) = make_uint2(pk(h0, h1), pk(h2, h3));
            *reinterpret_cast<uint2*>(buf + ASZ + r * AP + cc * 2) = make_uint2(pk(l0, l1), pk(l2, l3));
        }
        if (it < 63) {
            int kt = (it + 1) * 64;
            #pragma unroll
            for (int i = 0; i < 8; i++) {
                int p = tid * 4 + i * 1024;
                int r = p >> 6, cc = p & 63;
                areg[i] = *reinterpret_cast<const float4*>(A + (size_t)r * K + kt + cc);
            }
            uint32_t sb = s2u(sm) + ((it + 1) & 1) * STG + 2 * ASZ;
            #pragma unroll
            for (int i = 0; i < (2 * BCH) / 256; i++) {
                int q = tid + i * 256;
                int half = q >= BCH;
                int qq = q - half * BCH;
                int n = qq >> 3, c16 = qq & 7;
                const __nv_bfloat16* src = (half ? Bl : Bh) +
                    (size_t)(col0 + n) * 4096 + kt + c16 * 8;
                CP_ASYNC16(sb + half * BSZ + n * AP + c16 * 16, src);
            }
            CP_COMMIT();
            CP_WAIT1();
        } else {
            CP_WAIT0();
        }
        __syncthreads();

        uint32_t ab = s2u(buf);
        uint32_t aaddr = ab + a_row * AP + a_coff;
        uint32_t baddr = ab + 2 * ASZ + b_row * AP + b_coff;
        #pragma unroll
        for (int ks = 0; ks < 4; ks++) {
            uint32_t ah0, ah1, ah2, ah3, al0, al1, al2, al3;
            LDMX4(ah0, ah1, ah2, ah3, aaddr + ks * 32);
            LDMX4(al0, al1, al2, al3, aaddr + ASZ + ks * 32);
            #pragma unroll
            for (int j = 0; j < NT; j++) {
                uint32_t bh0, bh1, bl0, bl1;
                LDMX2(bh0, bh1, baddr + j * (8 * AP) + ks * 32);
                LDMX2(bl0, bl1, baddr + BSZ + j * (8 * AP) + ks * 32);
                MMA16816(c[j], ah0, ah1, ah2, ah3, bh0, bh1);
                MMA16816(c[j], ah0, ah1, ah2, ah3, bl0, bl1);
                MMA16816(c[j], al0, al1, al2, al3, bh0, bh1);
            }
        }
        __syncthreads();
    }

    // epilogue
    int rlo = row0 + warp * 16 + lane / 4;
    int rhi = rlo + 8;
    #pragma unroll
    for (int j = 0; j < NT; j++) {
        int col = col0 + j * 8 + (lane & 3) * 2;
        *reinterpret_cast<float2*>(C + (size_t)rlo * ldc + col) = make_float2(c[j][0], c[j][1]);
        *reinterpret_cast<float2*>(C + (size_t)rhi * ldc + col) = make_float2(c[j][2], c[j][3]);
    }
}

// ---------------- CSR build (by dst, with self loops) ----------------
__global__ void k_csr_init() {
    int i = blockIdx.x * 256 + threadIdx.x;
    if (i < NN) g_cur[i] = 1;
}

__global__ void k_csr_hist(const int* __restrict__ ei) {
    int i = blockIdx.x * 256 + threadIdx.x;
    atomicAdd(&g_cur[ei[EE + i]], 1);
}

__global__ void __launch_bounds__(1024) k_csr_scan() {
    int t = threadIdx.x;
    int b = t * 4;
    int c0 = g_cur[b], c1 = g_cur[b + 1], c2 = g_cur[b + 2], c3 = g_cur[b + 3];
    int s1 = c0 + c1, s2 = s1 + c2, tot = s2 + c3;
    int lane = t & 31, wid = t >> 5;
    int x = tot;
    #pragma unroll
    for (int o = 1; o < 32; o <<= 1) {
        int y = __shfl_up_sync(0xffffffffu, x, o);
        if (lane >= o) x += y;
    }
    __shared__ int ws[32];
    if (lane == 31) ws[wid] = x;
    __syncthreads();
    if (wid == 0) {
        int y = ws[lane];
        #pragma unroll
        for (int o = 1; o < 32; o <<= 1) {
            int z = __shfl_up_sync(0xffffffffu, y, o);
            if (lane >= o) y += z;
        }
        ws[lane] = y;
    }
    __syncthreads();
    int excl = x - tot + (wid ? ws[wid - 1] : 0);
    g_off[b] = excl; g_off[b + 1] = excl + c0; g_off[b + 2] = excl + s1; g_off[b + 3] = excl + s2;
    g_cur[b] = excl; g_cur[b + 1] = excl + c0; g_cur[b + 2] = excl + s1; g_cur[b + 3] = excl + s2;
    if (t == 1023) g_off[NN] = excl + tot;
}

__global__ void k_csr_scatter(const int* __restrict__ ei) {
    int i = blockIdx.x * 256 + threadIdx.x;
    int s, d;
    if (i < EE) { s = ei[i]; d = ei[EE + i]; }
    else        { s = d = i - EE; }
    int pos = atomicAdd(&g_cur[d], 1);
    g_csrc[pos] = s;
}

// ---------------- GAT: h, es, ed per branch ----------------
__global__ void __launch_bounds__(64)
k_h(const float* __restrict__ gat_W, const float* __restrict__ att_src,
    const float* __restrict__ att_dst)
{
    int g = blockIdx.y;
    int j = threadIdx.x;
    float w[32];
    #pragma unroll
    for (int k = 0; k < 32; k++) w[k] = gat_W[((size_t)g * 32 + k) * 64 + j];
    float as = att_src[g * 64 + j];
    float ad = att_dst[g * 64 + j];
    __shared__ float cof[32];
    for (int t = 0; t < 16; t++) {
        int n = blockIdx.x * 16 + t;
        if (j < 32) cof[j] = g_coefs[((size_t)g * NN + n) * FF + j];
        __syncthreads();
        float acc = 0.f;
        #pragma unroll
        for (int k = 0; k < 32; k++) acc += w[k] * cof[k];
        g_h[((size_t)g * NN + n) * HF + j] = acc;
        float vs = acc * as, vd = acc * ad;
        #pragma unroll
        for (int o = 16; o; o >>= 1) {
            vs += __shfl_xor_sync(0xffffffffu, vs, o);
            vd += __shfl_xor_sync(0xffffffffu, vd, o);
        }
        if ((j & 31) == 0) {
            g_es[((size_t)g * NN + n) * 2 + (j >> 5)] = vs;
            g_ed[((size_t)g * NN + n) * 2 + (j >> 5)] = vd;
        }
        __syncthreads();
    }
}

// ---------------- GAT aggregation + branch MLP ----------------
__global__ void __launch_bounds__(64)
k_agg(const float* __restrict__ gat_b, const float* __restrict__ mlp_W,
      const float* __restrict__ mlp_b)
{
    int n = blockIdx.x, g = blockIdx.y;
    int tid = threadIdx.x;
    int lane = tid & 31;
    int head = tid >> 5;
    int beg = g_off[n];
    int deg = g_off[n + 1] - beg;
    float2 edn = *reinterpret_cast<const float2*>(&g_ed[((size_t)g * NN + n) * 2]);

    float m0 = -1e30f, m1 = -1e30f;
    for (int i = tid; i < deg; i += 64) {
        int s = g_csrc[beg + i];
        float2 e = *reinterpret_cast<const float2*>(&g_es[((size_t)g * NN + s) * 2]);
        float e0 = e.x + edn.x; e0 = e0 > 0.f ? e0 : 0.2f * e0;
        float e1 = e.y + edn.y; e1 = e1 > 0.f ? e1 : 0.2f * e1;
        m0 = fmaxf(m0, e0); m1 = fmaxf(m1, e1);
    }
    #pragma unroll
    for (int o = 16; o; o >>= 1) {
        m0 = fmaxf(m0, __shfl_xor_sync(0xffffffffu, m0, o));
        m1 = fmaxf(m1, __shfl_xor_sync(0xffffffffu, m1, o));
    }
    __shared__ float pm0[2], pm1[2];
    if (lane == 0) { pm0[head] = m0; pm1[head] = m1; }
    __syncthreads();
    m0 = fmaxf(pm0[0], pm0[1]);
    m1 = fmaxf(pm1[0], pm1[1]);

    __shared__ float wbuf[2][32];
    __shared__ int   sbuf[32];
    float acc = 0.f, zp0 = 0.f, zp1 = 0.f;
    const float* hb = &g_h[(size_t)g * NN * HF];
    for (int c = 0; c < deg; c += 32) {
        __syncthreads();
        if (tid < 32) {
            int i = c + lane;
            float w0 = 0.f, w1 = 0.f; int s = 0;
            if (i < deg) {
                s = g_csrc[beg + i];
                float2 e = *reinterpret_cast<const float2*>(&g_es[((size_t)g * NN + s) * 2]);
                float e0 = e.x + edn.x; e0 = e0 > 0.f ? e0 : 0.2f * e0;
                float e1 = e.y + edn.y; e1 = e1 > 0.f ? e1 : 0.2f * e1;
                w0 = expf(e0 - m0); w1 = expf(e1 - m1);
            }
            wbuf[0][lane] = w0; wbuf[1][lane] = w1; sbuf[lane] = s;
            zp0 += w0; zp1 += w1;
        }
        __syncthreads();
        int lim = min(32, deg - c);
        for (int i = 0; i < lim; i++)
            acc += wbuf[head][i] * hb[(size_t)sbuf[i] * HF + tid];
    }
    __shared__ float sz[2];
    if (tid < 32) {
        #pragma unroll
        for (int o = 16; o; o >>= 1) {
            zp0 += __shfl_xor_sync(0xffffffffu, zp0, o);
            zp1 += __shfl_xor_sync(0xffffffffu, zp1, o);
        }
        if (lane == 0) { sz[0] = zp0; sz[1] = zp1; }
    }
    __syncthreads();
    float v = acc / (sz[head] + 1e-16f) + gat_b[g * HF + tid];
    v = v > 0.f ? v : expm1f(v);
    __shared__ float sh[64];
    sh[tid] = v;
    __syncthreads();
    float o = mlp_b[g * HF + tid];
    const float* mw = mlp_W + (size_t)g * HF * HF + tid;
    #pragma unroll 8
    for (int k = 0; k < 64; k++) o += sh[k] * mw[k * 64];
    g_feat[(size_t)n * (GG * HF) + g * HF + tid] = o;
}

// ---------------- final head + log_softmax ----------------
__global__ void __launch_bounds__(128)
k_out(const float* __restrict__ out_W, const float* __restrict__ out_b,
      float* __restrict__ out)
{
    int node = blockIdx.x * 4 + (threadIdx.x >> 5);
    int lane = threadIdx.x & 31;
    float acc[CC];
    #pragma unroll
    for (int c = 0; c < CC; c++) acc[c] = 0.f;
    const float* fr = &g_feat[(size_t)node * (GG * HF)];
    for (int k = lane; k < GG * HF; k += 32) {
        float v = fr[k];
        v = v > 0.f ? v : expm1f(v);
        #pragma unroll
        for (int c = 0; c < CC; c++) acc[c] += v * out_W[k * CC + c];
    }
    #pragma unroll
    for (int c = 0; c < CC; c++) {
        #pragma unroll
        for (int o = 16; o; o >>= 1)
            acc[c] += __shfl_xor_sync(0xffffffffu, acc[c], o);
        acc[c] += out_b[c];
    }
    float m = acc[0];
    #pragma unroll
    for (int c = 1; c < CC; c++) m = fmaxf(m, acc[c]);
    float s = 0.f;
    #pragma unroll
    for (int c = 0; c < CC; c++) s += expf(acc[c] - m);
    float lse = m + logf(s);
    if (lane < CC) out[(size_t)node * CC + lane] = acc[lane] - lse;
}

// ---------------- launcher ----------------
extern "C" void kernel_launch(void* const* d_in, const int* in_sizes, int n_in,
                              void* d_out, int out_size)
{
    const float* x       = (const float*)d_in[0];
    const int*   ei      = (const int*)  d_in[1];
    const float* U       = (const float*)d_in[2];
    const float* psi     = (const float*)d_in[3];
    const float* gat_W   = (const float*)d_in[4];
    const float* att_src = (const float*)d_in[5];
    const float* att_dst = (const float*)d_in[6];
    const float* gat_b   = (const float*)d_in[7];
    const float* mlp_W   = (const float*)d_in[8];
    const float* mlp_b   = (const float*)d_in[9];
    const float* out_W   = (const float*)d_in[10];
    const float* out_b   = (const float*)d_in[11];
    float* out = (float*)d_out;

    constexpr int SM32 = 2 * (2 * 128 * 144 + 2 * 32 * 144);   // 92160
    constexpr int SM96 = 2 * (2 * 128 * 144 + 2 * 96 * 144);   // 129024
    cudaFuncSetAttribute((const void*)k_gemm_mma<32>,
                         cudaFuncAttributeMaxDynamicSharedMemorySize, SM32);
    cudaFuncSetAttribute((const void*)k_gemm_mma<96>,
                         cudaFuncAttributeMaxDynamicSharedMemorySize, SM96);

    // CSR build (independent of GEMM chain)
    k_csr_init<<<16, 256>>>();
    k_csr_hist<<<EE / 256, 256>>>(ei);
    k_csr_scan<<<1, 1024>>>();
    k_csr_scatter<<<ETOT / 256, 256>>>(ei);

    // scattering-tree GEMM chain (mma.sync, 3xBF16)
    k_absT<<<128, dim3(32, 8)>>>(x);
    k_gemm_mma<32><<<dim3(128, 1), 256, SM32>>>(U, psi, 1, 0, 32);   // [U;psi]@af
    k_a1T<<<dim3(128, 3), dim3(32, 8)>>>();
    k_gemm_mma<96><<<dim3(128, 1), 256, SM96>>>(U, psi, 1, 1, 96);   // [U;psi]@|y1|
    k_b3T<<<dim3(128, 9), dim3(32, 8)>>>();
    k_gemm_mma<96><<<dim3(32, 3), 256, SM96>>>(U, psi, 0, 2, 288);   // U@|y2|
    k_coefs<<<(GG * NN * FF) / 256, 256>>>();

    // GAT branches + MLPs
    k_h<<<dim3(NN / 16, GG), 64>>>(gat_W, att_src, att_dst);
    k_agg<<<dim3(NN, GG), 64>>>(gat_b, mlp_W, mlp_b);

    // final head + log_softmax
    k_out<<<NN / 4, 128>>>(out_W, out_b, out);
}

// round 4
// speedup vs baseline: 2.2376x; 1.0079x over previous
#include <cuda_runtime.h>
#include <cuda_bf16.h>
#include <cstdint>

#define NN 4096
#define FF 32
#define HF 64
#define CC 10
#define GG 13
#define EE 65536
#define ETOT (EE + NN)   // 69632

// ---------------- scratch (static __device__, no allocation) ----------------
static __device__ __align__(16) float g_g1[4 * NN * FF];     // [U;psi] @ af   [16384][32]
static __device__ __align__(16) float g_g2[4 * NN * 96];     // [U;psi] @ a1   [16384][96]
static __device__ __align__(16) float g_g3[NN * 288];        // U @ b3         [4096][288]
static __device__ float g_coefs[GG * NN * FF];               // 13 coefficient maps
static __device__ __align__(16) __nv_bfloat16 g_afh[32 * NN],  g_afl[32 * NN];   // |x|^T split
static __device__ __align__(16) __nv_bfloat16 g_a1h[96 * NN],  g_a1l[96 * NN];   // |y1|^T split
static __device__ __align__(16) __nv_bfloat16 g_b3h[288 * NN], g_b3l[288 * NN];  // |y2|^T split
static __device__ float g_h[(size_t)GG * NN * HF];           // GAT h per branch
static __device__ float g_es[GG * NN * 2];
static __device__ float g_ed[GG * NN * 2];
static __device__ float g_feat[(size_t)NN * GG * HF];        // concat branch MLP outputs
static __device__ int   g_off[NN + 1];
static __device__ int   g_cur[NN];
static __device__ int   g_csrc[ETOT];

// ---------------- helpers ----------------
__device__ __forceinline__ void bf16split(float v, __nv_bfloat16& h, __nv_bfloat16& l) {
    h = __float2bfloat16_rn(v);
    l = __float2bfloat16_rn(v - __bfloat162float(h));
}
__device__ __forceinline__ uint32_t pk(__nv_bfloat16 a, __nv_bfloat16 b) {
    __nv_bfloat162 t = __halves2bfloat162(a, b);
    return *reinterpret_cast<uint32_t*>(&t);
}
__device__ __forceinline__ uint32_t s2u(const void* p) {
    uint32_t a;
    asm("{ .reg .u64 t; cvta.to.shared.u64 t, %1; cvt.u32.u64 %0, t; }" : "=r"(a) : "l"(p));
    return a;
}

#define CP_ASYNC16(saddr, gaddr) \
    asm volatile("cp.async.cg.shared.global [%0], [%1], 16;" :: "r"(saddr), "l"(gaddr))
#define CP_COMMIT() asm volatile("cp.async.commit_group;" ::: "memory")
#define CP_WAIT1()  asm volatile("cp.async.wait_group 1;" ::: "memory")
#define CP_WAIT0()  asm volatile("cp.async.wait_group 0;" ::: "memory")

#define LDMX4(r0, r1, r2, r3, a) \
    asm volatile("ldmatrix.sync.aligned.m8n8.x4.shared.b16 {%0,%1,%2,%3}, [%4];" \
                 : "=r"(r0), "=r"(r1), "=r"(r2), "=r"(r3) : "r"(a))
#define MMA16816(c, a0, a1, a2, a3, b0, b1) \
    asm volatile("mma.sync.aligned.m16n8k16.row.col.f32.bf16.bf16.f32 " \
                 "{%0,%1,%2,%3}, {%4,%5,%6,%7}, {%8,%9}, {%0,%1,%2,%3};" \
                 : "+f"((c)[0]), "+f"((c)[1]), "+f"((c)[2]), "+f"((c)[3]) \
                 : "r"(a0), "r"(a1), "r"(a2), "r"(a3), "r"(b0), "r"(b1))

// ---------------- transpose + abs + bf16-split repack kernels ----------------
__global__ void k_absT(const float* __restrict__ x) {
    __shared__ float s[32][33];
    int n0 = blockIdx.x * 32;
    int tx = threadIdx.x, ty = threadIdx.y;
    #pragma unroll
    for (int i = 0; i < 4; i++)
        s[ty + 8 * i][tx] = fabsf(x[(size_t)(n0 + ty + 8 * i) * 32 + tx]);
    __syncthreads();
    #pragma unroll
    for (int i = 0; i < 4; i++) {
        int f = ty + 8 * i;
        __nv_bfloat16 h, l; bf16split(s[tx][f], h, l);
        g_afh[(size_t)f * NN + n0 + tx] = h;
        g_afl[(size_t)f * NN + n0 + tx] = l;
    }
}

__global__ void k_a1T() {
    __shared__ float s[32][33];
    int n0 = blockIdx.x * 32, j = blockIdx.y;
    int tx = threadIdx.x, ty = threadIdx.y;
    #pragma unroll
    for (int i = 0; i < 4; i++)
        s[ty + 8 * i][tx] = fabsf(g_g1[((size_t)(1 + j) * NN + n0 + ty + 8 * i) * 32 + tx]);
    __syncthreads();
    #pragma unroll
    for (int i = 0; i < 4; i++) {
        int f = ty + 8 * i;
        __nv_bfloat16 h, l; bf16split(s[tx][f], h, l);
        g_a1h[(size_t)(j * 32 + f) * NN + n0 + tx] = h;
        g_a1l[(size_t)(j * 32 + f) * NN + n0 + tx] = l;
    }
}

__global__ void k_b3T() {
    __shared__ float s[32][33];
    int n0 = blockIdx.x * 32, y = blockIdx.y;          // y = j*3 + k
    int j = y / 3, k = y - 3 * j;
    int tx = threadIdx.x, ty = threadIdx.y;
    #pragma unroll
    for (int i = 0; i < 4; i++)
        s[ty + 8 * i][tx] = fabsf(g_g2[((size_t)(1 + k) * NN + n0 + ty + 8 * i) * 96 + j * 32 + tx]);
    __syncthreads();
    #pragma unroll
    for (int i = 0; i < 4; i++) {
        int f = ty + 8 * i;
        __nv_bfloat16 h, l; bf16split(s[tx][f], h, l);
        g_b3h[(size_t)(y * 32 + f) * NN + n0 + tx] = h;
        g_b3l[(size_t)(y * 32 + f) * NN + n0 + tx] = l;
    }
}

__global__ void k_coefs() {
    int i = blockIdx.x * 256 + threadIdx.x;            // GG*NN*FF
    int g = i / (NN * FF);
    int r = i - g * (NN * FF);
    int n = r >> 5, f = r & 31;
    float v;
    if (g == 0)      v = g_g1[(size_t)n * FF + f];
    else if (g < 4)  v = g_g2[(size_t)n * 96 + (g - 1) * 32 + f];
    else             v = g_g3[(size_t)n * 288 + (g - 4) * 32 + f];
    g_coefs[i] = v;
}

// ---------------- mma.sync 3xBF16 GEMM: C = [U(;psi)] @ B ----------------
// Block tile 128 x BN, K stage 64, 2-stage double buffer. 512 threads:
// 16 warps = 8 row-groups x 2 N-halves. A fp32 loaded+split in-kernel,
// B hi/lo bf16 [col][node] via cp.async. B operands via paired ldmatrix x4.
template<int BN>
__global__ void __launch_bounds__(512)
k_gemm_mma(const float* __restrict__ U, const float* __restrict__ psi,
           int usepsi, int sel, int ldc)
{
    extern __shared__ __align__(16) char sm[];
    constexpr int AP  = 144;                 // padded row pitch -> conflict-free ldmatrix
    constexpr int ASZ = 128 * AP;            // one A operand (hi or lo)
    constexpr int BSZ = BN * AP;
    constexpr int STG = 2 * ASZ + 2 * BSZ;   // Ahi | Alo | Bhi | Blo
    constexpr int CW  = BN / 2;              // cols per warp
    constexpr int NT  = CW / 8;              // n-tiles per warp
    constexpr int NP  = NT / 2;              // n-tile pairs per warp
    constexpr int BCH = BN * 8;              // 16B chunks per B operand per stage

    const int tid = threadIdx.x;
    const int warp = tid >> 5, lane = tid & 31;
    const int rw = warp & 7;                 // row group (16 rows)
    const int chh = warp >> 3;               // N half
    const int K = 4096;
    const int row0 = blockIdx.x * 128;
    const int col0 = blockIdx.y * BN;
    const float* __restrict__ A = (usepsi && row0 >= NN) ? psi + (size_t)(row0 - NN) * K
                                                         : U + (size_t)row0 * K;
    const __nv_bfloat16 *Bh, *Bl;
    float* C;
    if (sel == 0)      { Bh = g_afh; Bl = g_afl; C = g_g1; }
    else if (sel == 1) { Bh = g_a1h; Bl = g_a1l; C = g_g2; }
    else               { Bh = g_b3h; Bl = g_b3l; C = g_g3; }

    float c[NT][4];
    #pragma unroll
    for (int j = 0; j < NT; j++)
        #pragma unroll
        for (int q = 0; q < 4; q++) c[j][q] = 0.f;

    // A prefetch: 4 x float4 per thread over the 128x64 fp32 tile
    float4 areg[4];
    #pragma unroll
    for (int i = 0; i < 4; i++) {
        int p = tid * 4 + i * 2048;
        int r = p >> 6, cc = p & 63;
        areg[i] = *reinterpret_cast<const float4*>(A + (size_t)r * K + cc);
    }
    // B cp.async for stage 0
    {
        uint32_t sb = s2u(sm) + 2 * ASZ;
        #pragma unroll
        for (int i = 0; i < BN / 32; i++) {
            int q = tid + i * 512;
            int half = q >= BCH;
            int qq = q - half * BCH;
            int n = qq >> 3, c16 = qq & 7;
            const __nv_bfloat16* src = (half ? Bl : Bh) + (size_t)(col0 + n) * 4096 + c16 * 8;
            CP_ASYNC16(sb + half * BSZ + n * AP + c16 * 16, src);
        }
        CP_COMMIT();
    }

    // ldmatrix lane addressing (within-stage byte offsets)
    const int a_off  = (rw * 16 + (lane & 15)) * AP + (lane >> 4) * 16;
    const int b_off  = (chh * CW + (lane & 7) + ((lane >> 4) << 3)) * AP +
                       ((lane >> 3) & 1) * 16;

    for (int it = 0; it < 64; ++it) {
        char* buf = sm + (it & 1) * STG;
        // STS: split prefetched A regs into bf16 hi/lo
        #pragma unroll
        for (int i = 0; i < 4; i++) {
            int p = tid * 4 + i * 2048;
            int r = p >> 6, cc = p & 63;
            __nv_bfloat16 h0, h1, h2, h3, l0, l1, l2, l3;
            bf16split(areg[i].x, h0, l0); bf16split(areg[i].y, h1, l1);
            bf16split(areg[i].z, h2, l2); bf16split(areg[i].w, h3, l3);
            *reinterpret_cast<uint2*>(buf + r * AP + cc * 2) = make_uint2(pk(h0, h1), pk(h2, h3));
            *reinterpret_cast<uint2*>(buf + ASZ + r * AP + cc * 2) = make_uint2(pk(l0, l1), pk(l2, l3));
        }
        if (it < 63) {
            int kt = (it + 1) * 64;
            #pragma unroll
            for (int i = 0; i < 4; i++) {
                int p = tid * 4 + i * 2048;
                int r = p >> 6, cc = p & 63;
                areg[i] = *reinterpret_cast<const float4*>(A + (size_t)r * K + kt + cc);
            }
            uint32_t sb = s2u(sm) + ((it + 1) & 1) * STG + 2 * ASZ;
            #pragma unroll
            for (int i = 0; i < BN / 32; i++) {
                int q = tid + i * 512;
                int half = q >= BCH;
                int qq = q - half * BCH;
                int n = qq >> 3, c16 = qq & 7;
                const __nv_bfloat16* src = (half ? Bl : Bh) +
                    (size_t)(col0 + n) * 4096 + kt + c16 * 8;
                CP_ASYNC16(sb + half * BSZ + n * AP + c16 * 16, src);
            }
            CP_COMMIT();
            CP_WAIT1();
        } else {
            CP_WAIT0();
        }
        __syncthreads();

        uint32_t ab = s2u(buf);
        uint32_t aaddr  = ab + a_off;
        uint32_t bhaddr = ab + 2 * ASZ + b_off;
        uint32_t bladdr = bhaddr + BSZ;
        #pragma unroll
        for (int ks = 0; ks < 4; ks++) {
            uint32_t ah0, ah1, ah2, ah3, al0, al1, al2, al3;
            LDMX4(ah0, ah1, ah2, ah3, aaddr + ks * 32);
            LDMX4(al0, al1, al2, al3, aaddr + ASZ + ks * 32);
            #pragma unroll
            for (int jp = 0; jp < NP; jp++) {
                uint32_t bh0, bh1, bh2, bh3, bl0, bl1, bl2, bl3;
                LDMX4(bh0, bh1, bh2, bh3, bhaddr + jp * (16 * AP) + ks * 32);
                LDMX4(bl0, bl1, bl2, bl3, bladdr + jp * (16 * AP) + ks * 32);
                MMA16816(c[2 * jp],     ah0, ah1, ah2, ah3, bh0, bh1);
                MMA16816(c[2 * jp],     ah0, ah1, ah2, ah3, bl0, bl1);
                MMA16816(c[2 * jp],     al0, al1, al2, al3, bh0, bh1);
                MMA16816(c[2 * jp + 1], ah0, ah1, ah2, ah3, bh2, bh3);
                MMA16816(c[2 * jp + 1], ah0, ah1, ah2, ah3, bl2, bl3);
                MMA16816(c[2 * jp + 1], al0, al1, al2, al3, bh2, bh3);
            }
        }
        __syncthreads();
    }

    // epilogue
    int rlo = row0 + rw * 16 + lane / 4;
    int rhi = rlo + 8;
    #pragma unroll
    for (int j = 0; j < NT; j++) {
        int col = col0 + chh * CW + j * 8 + (lane & 3) * 2;
        *reinterpret_cast<float2*>(C + (size_t)rlo * ldc + col) = make_float2(c[j][0], c[j][1]);
        *reinterpret_cast<float2*>(C + (size_t)rhi * ldc + col) = make_float2(c[j][2], c[j][3]);
    }
}

// ---------------- CSR build (by dst, with self loops) ----------------
__global__ void k_csr_init() {
    int i = blockIdx.x * 256 + threadIdx.x;
    if (i < NN) g_cur[i] = 1;
}

__global__ void k_csr_hist(const int* __restrict__ ei) {
    int i = blockIdx.x * 256 + threadIdx.x;
    atomicAdd(&g_cur[ei[EE + i]], 1);
}

__global__ void __launch_bounds__(1024) k_csr_scan() {
    int t = threadIdx.x;
    int b = t * 4;
    int c0 = g_cur[b], c1 = g_cur[b + 1], c2 = g_cur[b + 2], c3 = g_cur[b + 3];
    int s1 = c0 + c1, s2 = s1 + c2, tot = s2 + c3;
    int lane = t & 31, wid = t >> 5;
    int x = tot;
    #pragma unroll
    for (int o = 1; o < 32; o <<= 1) {
        int y = __shfl_up_sync(0xffffffffu, x, o);
        if (lane >= o) x += y;
    }
    __shared__ int ws[32];
    if (lane == 31) ws[wid] = x;
    __syncthreads();
    if (wid == 0) {
        int y = ws[lane];
        #pragma unroll
        for (int o = 1; o < 32; o <<= 1) {
            int z = __shfl_up_sync(0xffffffffu, y, o);
            if (lane >= o) y += z;
        }
        ws[lane] = y;
    }
    __syncthreads();
    int excl = x - tot + (wid ? ws[wid - 1] : 0);
    g_off[b] = excl; g_off[b + 1] = excl + c0; g_off[b + 2] = excl + s1; g_off[b + 3] = excl + s2;
    g_cur[b] = excl; g_cur[b + 1] = excl + c0; g_cur[b + 2] = excl + s1; g_cur[b + 3] = excl + s2;
    if (t == 1023) g_off[NN] = excl + tot;
}

__global__ void k_csr_scatter(const int* __restrict__ ei) {
    int i = blockIdx.x * 256 + threadIdx.x;
    int s, d;
    if (i < EE) { s = ei[i]; d = ei[EE + i]; }
    else        { s = d = i - EE; }
    int pos = atomicAdd(&g_cur[d], 1);
    g_csrc[pos] = s;
}

// ---------------- GAT: h, es, ed per branch ----------------
__global__ void __launch_bounds__(64)
k_h(const float* __restrict__ gat_W, const float* __restrict__ att_src,
    const float* __restrict__ att_dst)
{
    int g = blockIdx.y;
    int j = threadIdx.x;
    float w[32];
    #pragma unroll
    for (int k = 0; k < 32; k++) w[k] = gat_W[((size_t)g * 32 + k) * 64 + j];
    float as = att_src[g * 64 + j];
    float ad = att_dst[g * 64 + j];
    __shared__ float cof[32];
    for (int t = 0; t < 16; t++) {
        int n = blockIdx.x * 16 + t;
        if (j < 32) cof[j] = g_coefs[((size_t)g * NN + n) * FF + j];
        __syncthreads();
        float acc = 0.f;
        #pragma unroll
        for (int k = 0; k < 32; k++) acc += w[k] * cof[k];
        g_h[((size_t)g * NN + n) * HF + j] = acc;
        float vs = acc * as, vd = acc * ad;
        #pragma unroll
        for (int o = 16; o; o >>= 1) {
            vs += __shfl_xor_sync(0xffffffffu, vs, o);
            vd += __shfl_xor_sync(0xffffffffu, vd, o);
        }
        if ((j & 31) == 0) {
            g_es[((size_t)g * NN + n) * 2 + (j >> 5)] = vs;
            g_ed[((size_t)g * NN + n) * 2 + (j >> 5)] = vd;
        }
        __syncthreads();
    }
}

// ---------------- GAT aggregation + branch MLP ----------------
__global__ void __launch_bounds__(64)
k_agg(const float* __restrict__ gat_b, const float* __restrict__ mlp_W,
      const float* __restrict__ mlp_b)
{
    int n = blockIdx.x, g = blockIdx.y;
    int tid = threadIdx.x;
    int lane = tid & 31;
    int head = tid >> 5;
    int beg = g_off[n];
    int deg = g_off[n + 1] - beg;
    float2 edn = *reinterpret_cast<const float2*>(&g_ed[((size_t)g * NN + n) * 2]);

    float m0 = -1e30f, m1 = -1e30f;
    for (int i = tid; i < deg; i += 64) {
        int s = g_csrc[beg + i];
        float2 e = *reinterpret_cast<const float2*>(&g_es[((size_t)g * NN + s) * 2]);
        float e0 = e.x + edn.x; e0 = e0 > 0.f ? e0 : 0.2f * e0;
        float e1 = e.y + edn.y; e1 = e1 > 0.f ? e1 : 0.2f * e1;
        m0 = fmaxf(m0, e0); m1 = fmaxf(m1, e1);
    }
    #pragma unroll
    for (int o = 16; o; o >>= 1) {
        m0 = fmaxf(m0, __shfl_xor_sync(0xffffffffu, m0, o));
        m1 = fmaxf(m1, __shfl_xor_sync(0xffffffffu, m1, o));
    }
    __shared__ float pm0[2], pm1[2];
    if (lane == 0) { pm0[head] = m0; pm1[head] = m1; }
    __syncthreads();
    m0 = fmaxf(pm0[0], pm0[1]);
    m1 = fmaxf(pm1[0], pm1[1]);

    __shared__ float wbuf[2][32];
    __shared__ int   sbuf[32];
    float acc = 0.f, zp0 = 0.f, zp1 = 0.f;
    const float* hb = &g_h[(size_t)g * NN * HF];
    for (int c = 0; c < deg; c += 32) {
        __syncthreads();
        if (tid < 32) {
            int i = c + lane;
            float w0 = 0.f, w1 = 0.f; int s = 0;
            if (i < deg) {
                s = g_csrc[beg + i];
                float2 e = *reinterpret_cast<const float2*>(&g_es[((size_t)g * NN + s) * 2]);
                float e0 = e.x + edn.x; e0 = e0 > 0.f ? e0 : 0.2f * e0;
                float e1 = e.y + edn.y; e1 = e1 > 0.f ? e1 : 0.2f * e1;
                w0 = expf(e0 - m0); w1 = expf(e1 - m1);
            }
            wbuf[0][lane] = w0; wbuf[1][lane] = w1; sbuf[lane] = s;
            zp0 += w0; zp1 += w1;
        }
        __syncthreads();
        int lim = min(32, deg - c);
        for (int i = 0; i < lim; i++)
            acc += wbuf[head][i] * hb[(size_t)sbuf[i] * HF + tid];
    }
    __shared__ float sz[2];
    if (tid < 32) {
        #pragma unroll
        for (int o = 16; o; o >>= 1) {
            zp0 += __shfl_xor_sync(0xffffffffu, zp0, o);
            zp1 += __shfl_xor_sync(0xffffffffu, zp1, o);
        }
        if (lane == 0) { sz[0] = zp0; sz[1] = zp1; }
    }
    __syncthreads();
    float v = acc / (sz[head] + 1e-16f) + gat_b[g * HF + tid];
    v = v > 0.f ? v : expm1f(v);
    __shared__ float sh[64];
    sh[tid] = v;
    __syncthreads();
    float o = mlp_b[g * HF + tid];
    const float* mw = mlp_W + (size_t)g * HF * HF + tid;
    #pragma unroll 8
    for (int k = 0; k < 64; k++) o += sh[k] * mw[k * 64];
    g_feat[(size_t)n * (GG * HF) + g * HF + tid] = o;
}

// ---------------- final head + log_softmax ----------------
__global__ void __launch_bounds__(128)
k_out(const float* __restrict__ out_W, const float* __restrict__ out_b,
      float* __restrict__ out)
{
    int node = blockIdx.x * 4 + (threadIdx.x >> 5);
    int lane = threadIdx.x & 31;
    float acc[CC];
    #pragma unroll
    for (int c = 0; c < CC; c++) acc[c] = 0.f;
    const float* fr = &g_feat[(size_t)node * (GG * HF)];
    for (int k = lane; k < GG * HF; k += 32) {
        float v = fr[k];
        v = v > 0.f ? v : expm1f(v);
        #pragma unroll
        for (int c = 0; c < CC; c++) acc[c] += v * out_W[k * CC + c];
    }
    #pragma unroll
    for (int c = 0; c < CC; c++) {
        #pragma unroll
        for (int o = 16; o; o >>= 1)
            acc[c] += __shfl_xor_sync(0xffffffffu, acc[c], o);
        acc[c] += out_b[c];
    }
    float m = acc[0];
    #pragma unroll
    for (int c = 1; c < CC; c++) m = fmaxf(m, acc[c]);
    float s = 0.f;
    #pragma unroll
    for (int c = 0; c < CC; c++) s += expf(acc[c] - m);
    float lse = m + logf(s);
    if (lane < CC) out[(size_t)node * CC + lane] = acc[lane] - lse;
}

// ---------------- launcher ----------------
extern "C" void kernel_launch(void* const* d_in, const int* in_sizes, int n_in,
                              void* d_out, int out_size)
{
    const float* x       = (const float*)d_in[0];
    const int*   ei      = (const int*)  d_in[1];
    const float* U       = (const float*)d_in[2];
    const float* psi     = (const float*)d_in[3];
    const float* gat_W   = (const float*)d_in[4];
    const float* att_src = (const float*)d_in[5];
    const float* att_dst = (const float*)d_in[6];
    const float* gat_b   = (const float*)d_in[7];
    const float* mlp_W   = (const float*)d_in[8];
    const float* mlp_b   = (const float*)d_in[9];
    const float* out_W   = (const float*)d_in[10];
    const float* out_b   = (const float*)d_in[11];
    float* out = (float*)d_out;

    constexpr int SM32 = 2 * (2 * 128 * 144 + 2 * 32 * 144);   // 92160
    constexpr int SM96 = 2 * (2 * 128 * 144 + 2 * 96 * 144);   // 129024
    cudaFuncSetAttribute((const void*)k_gemm_mma<32>,
                         cudaFuncAttributeMaxDynamicSharedMemorySize, SM32);
    cudaFuncSetAttribute((const void*)k_gemm_mma<96>,
                         cudaFuncAttributeMaxDynamicSharedMemorySize, SM96);

    // scattering-tree GEMM chain first (mma.sync, 3xBF16)
    k_absT<<<128, dim3(32, 8)>>>(x);
    k_gemm_mma<32><<<dim3(128, 1), 512, SM32>>>(U, psi, 1, 0, 32);   // [U;psi]@af
    k_a1T<<<dim3(128, 3), dim3(32, 8)>>>();
    k_gemm_mma<96><<<dim3(128, 1), 512, SM96>>>(U, psi, 1, 1, 96);   // [U;psi]@|y1|
    k_b3T<<<dim3(128, 9), dim3(32, 8)>>>();
    k_gemm_mma<96><<<dim3(32, 3), 512, SM96>>>(U, psi, 0, 2, 288);   // U@|y2|
    k_coefs<<<(GG * NN * FF) / 256, 256>>>();

    // CSR build (only needed before k_agg)
    k_csr_init<<<16, 256>>>();
    k_csr_hist<<<EE / 256, 256>>>(ei);
    k_csr_scan<<<1, 1024>>>();
    k_csr_scatter<<<ETOT / 256, 256>>>(ei);

    // GAT branches + MLPs
    k_h<<<dim3(NN / 16, GG), 64>>>(gat_W, att_src, att_dst);
    k_agg<<<dim3(NN, GG), 64>>>(gat_b, mlp_W, mlp_b);

    // final head + log_softmax
    k_out<<<NN / 4, 128>>>(out_W, out_b, out);
}

// round 5
// speedup vs baseline: 2.2838x; 1.0207x over previous
#include <cuda_runtime.h>
#include <cuda_bf16.h>
#include <cstdint>

#define NN 4096
#define FF 32
#define HF 64
#define CC 10
#define GG 13
#define EE 65536
#define ETOT (EE + NN)   // 69632

// ---------------- scratch (static __device__, no allocation) ----------------
static __device__ __align__(16) float g_g1[4 * NN * FF];     // [U;psi] @ af   [16384][32]
static __device__ __align__(16) float g_g2[4 * NN * 96];     // [U;psi] @ a1   [16384][96]
static __device__ __align__(16) float g_g3[NN * 288];        // U @ b3         [4096][288]
static __device__ float g_coefs[GG * NN * FF];               // 13 coefficient maps
static __device__ __align__(16) __nv_bfloat16 g_afh[32 * NN],  g_afl[32 * NN];   // |x|^T split
static __device__ __align__(16) __nv_bfloat16 g_a1h[96 * NN],  g_a1l[96 * NN];   // |y1|^T split
static __device__ __align__(16) __nv_bfloat16 g_b3h[288 * NN], g_b3l[288 * NN];  // |y2|^T split
static __device__ float g_h[(size_t)GG * NN * HF];           // GAT h per branch
static __device__ float g_es[GG * NN * 2];
static __device__ float g_ed[GG * NN * 2];
static __device__ float g_feat[(size_t)NN * GG * HF];        // concat branch MLP outputs
static __device__ int   g_off[NN + 1];
static __device__ int   g_cur[NN];
static __device__ int   g_csrc[ETOT];

// ---------------- helpers ----------------
__device__ __forceinline__ void bf16split(float v, __nv_bfloat16& h, __nv_bfloat16& l) {
    h = __float2bfloat16_rn(v);
    l = __float2bfloat16_rn(v - __bfloat162float(h));
}
__device__ __forceinline__ uint32_t pk(__nv_bfloat16 a, __nv_bfloat16 b) {
    __nv_bfloat162 t = __halves2bfloat162(a, b);
    return *reinterpret_cast<uint32_t*>(&t);
}
__device__ __forceinline__ uint32_t s2u(const void* p) {
    uint32_t a;
    asm("{ .reg .u64 t; cvta.to.shared.u64 t, %1; cvt.u32.u64 %0, t; }" : "=r"(a) : "l"(p));
    return a;
}

#define CP_ASYNC16(saddr, gaddr) \
    asm volatile("cp.async.cg.shared.global [%0], [%1], 16;" :: "r"(saddr), "l"(gaddr))
#define CP_COMMIT() asm volatile("cp.async.commit_group;" ::: "memory")
#define CP_WAIT1()  asm volatile("cp.async.wait_group 1;" ::: "memory")
#define CP_WAIT0()  asm volatile("cp.async.wait_group 0;" ::: "memory")

#define LDMX4(r0, r1, r2, r3, a) \
    asm volatile("ldmatrix.sync.aligned.m8n8.x4.shared.b16 {%0,%1,%2,%3}, [%4];" \
                 : "=r"(r0), "=r"(r1), "=r"(r2), "=r"(r3) : "r"(a))
#define MMA16816(c, a0, a1, a2, a3, b0, b1) \
    asm volatile("mma.sync.aligned.m16n8k16.row.col.f32.bf16.bf16.f32 " \
                 "{%0,%1,%2,%3}, {%4,%5,%6,%7}, {%8,%9}, {%0,%1,%2,%3};" \
                 : "+f"((c)[0]), "+f"((c)[1]), "+f"((c)[2]), "+f"((c)[3]) \
                 : "r"(a0), "r"(a1), "r"(a2), "r"(a3), "r"(b0), "r"(b1))

// ---------------- transpose + abs + bf16-split repack kernels ----------------
__global__ void k_absT(const float* __restrict__ x) {
    __shared__ float s[32][33];
    int n0 = blockIdx.x * 32;
    int tx = threadIdx.x, ty = threadIdx.y;
    #pragma unroll
    for (int i = 0; i < 4; i++)
        s[ty + 8 * i][tx] = fabsf(x[(size_t)(n0 + ty + 8 * i) * 32 + tx]);
    __syncthreads();
    #pragma unroll
    for (int i = 0; i < 4; i++) {
        int f = ty + 8 * i;
        __nv_bfloat16 h, l; bf16split(s[tx][f], h, l);
        g_afh[(size_t)f * NN + n0 + tx] = h;
        g_afl[(size_t)f * NN + n0 + tx] = l;
    }
}

__global__ void k_a1T() {
    __shared__ float s[32][33];
    int n0 = blockIdx.x * 32, j = blockIdx.y;
    int tx = threadIdx.x, ty = threadIdx.y;
    #pragma unroll
    for (int i = 0; i < 4; i++)
        s[ty + 8 * i][tx] = fabsf(g_g1[((size_t)(1 + j) * NN + n0 + ty + 8 * i) * 32 + tx]);
    __syncthreads();
    #pragma unroll
    for (int i = 0; i < 4; i++) {
        int f = ty + 8 * i;
        __nv_bfloat16 h, l; bf16split(s[tx][f], h, l);
        g_a1h[(size_t)(j * 32 + f) * NN + n0 + tx] = h;
        g_a1l[(size_t)(j * 32 + f) * NN + n0 + tx] = l;
    }
}

__global__ void k_b3T() {
    __shared__ float s[32][33];
    int n0 = blockIdx.x * 32, y = blockIdx.y;          // y = j*3 + k
    int j = y / 3, k = y - 3 * j;
    int tx = threadIdx.x, ty = threadIdx.y;
    #pragma unroll
    for (int i = 0; i < 4; i++)
        s[ty + 8 * i][tx] = fabsf(g_g2[((size_t)(1 + k) * NN + n0 + ty + 8 * i) * 96 + j * 32 + tx]);
    __syncthreads();
    #pragma unroll
    for (int i = 0; i < 4; i++) {
        int f = ty + 8 * i;
        __nv_bfloat16 h, l; bf16split(s[tx][f], h, l);
        g_b3h[(size_t)(y * 32 + f) * NN + n0 + tx] = h;
        g_b3l[(size_t)(y * 32 + f) * NN + n0 + tx] = l;
    }
}

__global__ void k_coefs() {
    int i = blockIdx.x * 256 + threadIdx.x;            // GG*NN*FF
    int g = i / (NN * FF);
    int r = i - g * (NN * FF);
    int n = r >> 5, f = r & 31;
    float v;
    if (g == 0)      v = g_g1[(size_t)n * FF + f];
    else if (g < 4)  v = g_g2[(size_t)n * 96 + (g - 1) * 32 + f];
    else             v = g_g3[(size_t)n * 288 + (g - 4) * 32 + f];
    g_coefs[i] = v;
}

// ---------------- mma.sync 3xBF16 GEMM: C = [U(;psi)] @ B ----------------
// Block tile 128 x BN, K stage 64, 2-stage double buffer. 256 threads / 8 warps:
// warp grid R=4 row-groups (32 rows) x C=2 col-halves -> minimal smem operand
// re-reads (LDS/iter = 2*A + 4*B instead of 2*A + 8*B).
template<int BN>
__global__ void __launch_bounds__(256)
k_gemm_mma(const float* __restrict__ U, const float* __restrict__ psi,
           int usepsi, int sel, int ldc)
{
    extern __shared__ __align__(16) char sm[];
    constexpr int AP  = 144;                 // padded row pitch -> conflict-free ldmatrix
    constexpr int ASZ = 128 * AP;            // one A operand (hi or lo)
    constexpr int BSZ = BN * AP;
    constexpr int STG = 2 * ASZ + 2 * BSZ;   // Ahi | Alo | Bhi | Blo
    constexpr int CW  = BN / 2;              // cols per warp
    constexpr int NT  = CW / 8;              // n-tiles per warp
    constexpr int NP  = NT / 2;              // n-tile pairs per warp
    constexpr int BCH = BN * 8;              // 16B chunks per B operand per stage

    const int tid = threadIdx.x;
    const int warp = tid >> 5, lane = tid & 31;
    const int rw = warp & 3;                 // row group (32 rows)
    const int chh = warp >> 2;               // N half
    const int K = 4096;
    const int row0 = blockIdx.x * 128;
    const int col0 = blockIdx.y * BN;
    const float* __restrict__ A = (usepsi && row0 >= NN) ? psi + (size_t)(row0 - NN) * K
                                                         : U + (size_t)row0 * K;
    const __nv_bfloat16 *Bh, *Bl;
    float* C;
    if (sel == 0)      { Bh = g_afh; Bl = g_afl; C = g_g1; }
    else if (sel == 1) { Bh = g_a1h; Bl = g_a1l; C = g_g2; }
    else               { Bh = g_b3h; Bl = g_b3l; C = g_g3; }

    float c[2][NT][4];
    #pragma unroll
    for (int m = 0; m < 2; m++)
        #pragma unroll
        for (int j = 0; j < NT; j++)
            #pragma unroll
            for (int q = 0; q < 4; q++) c[m][j][q] = 0.f;

    // A prefetch: 8 x float4 per thread over the 128x64 fp32 tile
    float4 areg[8];
    #pragma unroll
    for (int i = 0; i < 8; i++) {
        int p = tid * 4 + i * 1024;
        int r = p >> 6, cc = p & 63;
        areg[i] = *reinterpret_cast<const float4*>(A + (size_t)r * K + cc);
    }
    // B cp.async for stage 0
    {
        uint32_t sb = s2u(sm) + 2 * ASZ;
        #pragma unroll
        for (int i = 0; i < BN / 16; i++) {
            int q = tid + i * 256;
            int half = q >= BCH;
            int qq = q - half * BCH;
            int n = qq >> 3, c16 = qq & 7;
            const __nv_bfloat16* src = (half ? Bl : Bh) + (size_t)(col0 + n) * 4096 + c16 * 8;
            CP_ASYNC16(sb + half * BSZ + n * AP + c16 * 16, src);
        }
        CP_COMMIT();
    }

    // ldmatrix lane addressing (within-stage byte offsets)
    const int a_off0 = (rw * 32 + (lane & 15)) * AP + (lane >> 4) * 16;
    const int a_off1 = a_off0 + 16 * AP;
    const int b_off  = (chh * CW + (lane & 7) + ((lane >> 4) << 3)) * AP +
                       ((lane >> 3) & 1) * 16;

    for (int it = 0; it < 64; ++it) {
        char* buf = sm + (it & 1) * STG;
        // STS: split prefetched A regs into bf16 hi/lo
        #pragma unroll
        for (int i = 0; i < 8; i++) {
            int p = tid * 4 + i * 1024;
            int r = p >> 6, cc = p & 63;
            __nv_bfloat16 h0, h1, h2, h3, l0, l1, l2, l3;
            bf16split(areg[i].x, h0, l0); bf16split(areg[i].y, h1, l1);
            bf16split(areg[i].z, h2, l2); bf16split(areg[i].w, h3, l3);
            *reinterpret_cast<uint2*>(buf + r * AP + cc * 2) = make_uint2(pk(h0, h1), pk(h2, h3));
            *reinterpret_cast<uint2*>(buf + ASZ + r * AP + cc * 2) = make_uint2(pk(l0, l1), pk(l2, l3));
        }
        if (it < 63) {
            int kt = (it + 1) * 64;
            #pragma unroll
            for (int i = 0; i < 8; i++) {
                int p = tid * 4 + i * 1024;
                int r = p >> 6, cc = p & 63;
                areg[i] = *reinterpret_cast<const float4*>(A + (size_t)r * K + kt + cc);
            }
            uint32_t sb = s2u(sm) + ((it + 1) & 1) * STG + 2 * ASZ;
            #pragma unroll
            for (int i = 0; i < BN / 16; i++) {
                int q = tid + i * 256;
                int half = q >= BCH;
                int qq = q - half * BCH;
                int n = qq >> 3, c16 = qq & 7;
                const __nv_bfloat16* src = (half ? Bl : Bh) +
                    (size_t)(col0 + n) * 4096 + kt + c16 * 8;
                CP_ASYNC16(sb + half * BSZ + n * AP + c16 * 16, src);
            }
            CP_COMMIT();
            CP_WAIT1();
        } else {
            CP_WAIT0();
        }
        __syncthreads();

        uint32_t ab = s2u(buf);
        uint32_t a0addr = ab + a_off0;
        uint32_t a1addr = ab + a_off1;
        uint32_t bhaddr = ab + 2 * ASZ + b_off;
        uint32_t bladdr = bhaddr + BSZ;
        #pragma unroll
        for (int ks = 0; ks < 4; ks++) {
            uint32_t x0h0, x0h1, x0h2, x0h3, x0l0, x0l1, x0l2, x0l3;
            uint32_t x1h0, x1h1, x1h2, x1h3, x1l0, x1l1, x1l2, x1l3;
            LDMX4(x0h0, x0h1, x0h2, x0h3, a0addr + ks * 32);
            LDMX4(x0l0, x0l1, x0l2, x0l3, a0addr + ASZ + ks * 32);
            LDMX4(x1h0, x1h1, x1h2, x1h3, a1addr + ks * 32);
            LDMX4(x1l0, x1l1, x1l2, x1l3, a1addr + ASZ + ks * 32);
            #pragma unroll
            for (int jp = 0; jp < NP; jp++) {
                uint32_t bh0, bh1, bh2, bh3, bl0, bl1, bl2, bl3;
                LDMX4(bh0, bh1, bh2, bh3, bhaddr + jp * (16 * AP) + ks * 32);
                LDMX4(bl0, bl1, bl2, bl3, bladdr + jp * (16 * AP) + ks * 32);
                MMA16816(c[0][2 * jp],     x0h0, x0h1, x0h2, x0h3, bh0, bh1);
                MMA16816(c[0][2 * jp],     x0h0, x0h1, x0h2, x0h3, bl0, bl1);
                MMA16816(c[0][2 * jp],     x0l0, x0l1, x0l2, x0l3, bh0, bh1);
                MMA16816(c[1][2 * jp],     x1h0, x1h1, x1h2, x1h3, bh0, bh1);
                MMA16816(c[1][2 * jp],     x1h0, x1h1, x1h2, x1h3, bl0, bl1);
                MMA16816(c[1][2 * jp],     x1l0, x1l1, x1l2, x1l3, bh0, bh1);
                MMA16816(c[0][2 * jp + 1], x0h0, x0h1, x0h2, x0h3, bh2, bh3);
                MMA16816(c[0][2 * jp + 1], x0h0, x0h1, x0h2, x0h3, bl2, bl3);
                MMA16816(c[0][2 * jp + 1], x0l0, x0l1, x0l2, x0l3, bh2, bh3);
                MMA16816(c[1][2 * jp + 1], x1h0, x1h1, x1h2, x1h3, bh2, bh3);
                MMA16816(c[1][2 * jp + 1], x1h0, x1h1, x1h2, x1h3, bl2, bl3);
                MMA16816(c[1][2 * jp + 1], x1l0, x1l1, x1l2, x1l3, bh2, bh3);
            }
        }
        __syncthreads();
    }

    // epilogue
    #pragma unroll
    for (int m = 0; m < 2; m++) {
        int rlo = row0 + rw * 32 + m * 16 + lane / 4;
        int rhi = rlo + 8;
        #pragma unroll
        for (int j = 0; j < NT; j++) {
            int col = col0 + chh * CW + j * 8 + (lane & 3) * 2;
            *reinterpret_cast<float2*>(C + (size_t)rlo * ldc + col) =
                make_float2(c[m][j][0], c[m][j][1]);
            *reinterpret_cast<float2*>(C + (size_t)rhi * ldc + col) =
                make_float2(c[m][j][2], c[m][j][3]);
        }
    }
}

// ---------------- CSR build (by dst, with self loops) ----------------
__global__ void k_csr_init() {
    int i = blockIdx.x * 256 + threadIdx.x;
    if (i < NN) g_cur[i] = 1;
}

__global__ void k_csr_hist(const int* __restrict__ ei) {
    int i = blockIdx.x * 256 + threadIdx.x;
    atomicAdd(&g_cur[ei[EE + i]], 1);
}

__global__ void __launch_bounds__(1024) k_csr_scan() {
    int t = threadIdx.x;
    int b = t * 4;
    int c0 = g_cur[b], c1 = g_cur[b + 1], c2 = g_cur[b + 2], c3 = g_cur[b + 3];
    int s1 = c0 + c1, s2 = s1 + c2, tot = s2 + c3;
    int lane = t & 31, wid = t >> 5;
    int x = tot;
    #pragma unroll
    for (int o = 1; o < 32; o <<= 1) {
        int y = __shfl_up_sync(0xffffffffu, x, o);
        if (lane >= o) x += y;
    }
    __shared__ int ws[32];
    if (lane == 31) ws[wid] = x;
    __syncthreads();
    if (wid == 0) {
        int y = ws[lane];
        #pragma unroll
        for (int o = 1; o < 32; o <<= 1) {
            int z = __shfl_up_sync(0xffffffffu, y, o);
            if (lane >= o) y += z;
        }
        ws[lane] = y;
    }
    __syncthreads();
    int excl = x - tot + (wid ? ws[wid - 1] : 0);
    g_off[b] = excl; g_off[b + 1] = excl + c0; g_off[b + 2] = excl + s1; g_off[b + 3] = excl + s2;
    g_cur[b] = excl; g_cur[b + 1] = excl + c0; g_cur[b + 2] = excl + s1; g_cur[b + 3] = excl + s2;
    if (t == 1023) g_off[NN] = excl + tot;
}

__global__ void k_csr_scatter(const int* __restrict__ ei) {
    int i = blockIdx.x * 256 + threadIdx.x;
    int s, d;
    if (i < EE) { s = ei[i]; d = ei[EE + i]; }
    else        { s = d = i - EE; }
    int pos = atomicAdd(&g_cur[d], 1);
    g_csrc[pos] = s;
}

// ---------------- GAT: h, es, ed per branch ----------------
__global__ void __launch_bounds__(64)
k_h(const float* __restrict__ gat_W, const float* __restrict__ att_src,
    const float* __restrict__ att_dst)
{
    int g = blockIdx.y;
    int j = threadIdx.x;
    float w[32];
    #pragma unroll
    for (int k = 0; k < 32; k++) w[k] = gat_W[((size_t)g * 32 + k) * 64 + j];
    float as = att_src[g * 64 + j];
    float ad = att_dst[g * 64 + j];
    __shared__ float cof[32];
    for (int t = 0; t < 16; t++) {
        int n = blockIdx.x * 16 + t;
        if (j < 32) cof[j] = g_coefs[((size_t)g * NN + n) * FF + j];
        __syncthreads();
        float acc = 0.f;
        #pragma unroll
        for (int k = 0; k < 32; k++) acc += w[k] * cof[k];
        g_h[((size_t)g * NN + n) * HF + j] = acc;
        float vs = acc * as, vd = acc * ad;
        #pragma unroll
        for (int o = 16; o; o >>= 1) {
            vs += __shfl_xor_sync(0xffffffffu, vs, o);
            vd += __shfl_xor_sync(0xffffffffu, vd, o);
        }
        if ((j & 31) == 0) {
            g_es[((size_t)g * NN + n) * 2 + (j >> 5)] = vs;
            g_ed[((size_t)g * NN + n) * 2 + (j >> 5)] = vd;
        }
        __syncthreads();
    }
}

// ---------------- GAT aggregation + branch MLP ----------------
__global__ void __launch_bounds__(64)
k_agg(const float* __restrict__ gat_b, const float* __restrict__ mlp_W,
      const float* __restrict__ mlp_b)
{
    int n = blockIdx.x, g = blockIdx.y;
    int tid = threadIdx.x;
    int lane = tid & 31;
    int head = tid >> 5;
    int beg = g_off[n];
    int deg = g_off[n + 1] - beg;
    float2 edn = *reinterpret_cast<const float2*>(&g_ed[((size_t)g * NN + n) * 2]);

    float m0 = -1e30f, m1 = -1e30f;
    for (int i = tid; i < deg; i += 64) {
        int s = g_csrc[beg + i];
        float2 e = *reinterpret_cast<const float2*>(&g_es[((size_t)g * NN + s) * 2]);
        float e0 = e.x + edn.x; e0 = e0 > 0.f ? e0 : 0.2f * e0;
        float e1 = e.y + edn.y; e1 = e1 > 0.f ? e1 : 0.2f * e1;
        m0 = fmaxf(m0, e0); m1 = fmaxf(m1, e1);
    }
    #pragma unroll
    for (int o = 16; o; o >>= 1) {
        m0 = fmaxf(m0, __shfl_xor_sync(0xffffffffu, m0, o));
        m1 = fmaxf(m1, __shfl_xor_sync(0xffffffffu, m1, o));
    }
    __shared__ float pm0[2], pm1[2];
    if (lane == 0) { pm0[head] = m0; pm1[head] = m1; }
    __syncthreads();
    m0 = fmaxf(pm0[0], pm0[1]);
    m1 = fmaxf(pm1[0], pm1[1]);

    __shared__ float wbuf[2][32];
    __shared__ int   sbuf[32];
    float acc = 0.f, zp0 = 0.f, zp1 = 0.f;
    const float* hb = &g_h[(size_t)g * NN * HF];
    for (int c = 0; c < deg; c += 32) {
        __syncthreads();
        if (tid < 32) {
            int i = c + lane;
            float w0 = 0.f, w1 = 0.f; int s = 0;
            if (i < deg) {
                s = g_csrc[beg + i];
                float2 e = *reinterpret_cast<const float2*>(&g_es[((size_t)g * NN + s) * 2]);
                float e0 = e.x + edn.x; e0 = e0 > 0.f ? e0 : 0.2f * e0;
                float e1 = e.y + edn.y; e1 = e1 > 0.f ? e1 : 0.2f * e1;
                w0 = expf(e0 - m0); w1 = expf(e1 - m1);
            }
            wbuf[0][lane] = w0; wbuf[1][lane] = w1; sbuf[lane] = s;
            zp0 += w0; zp1 += w1;
        }
        __syncthreads();
        int lim = min(32, deg - c);
        for (int i = 0; i < lim; i++)
            acc += wbuf[head][i] * hb[(size_t)sbuf[i] * HF + tid];
    }
    __shared__ float sz[2];
    if (tid < 32) {
        #pragma unroll
        for (int o = 16; o; o >>= 1) {
            zp0 += __shfl_xor_sync(0xffffffffu, zp0, o);
            zp1 += __shfl_xor_sync(0xffffffffu, zp1, o);
        }
        if (lane == 0) { sz[0] = zp0; sz[1] = zp1; }
    }
    __syncthreads();
    float v = acc / (sz[head] + 1e-16f) + gat_b[g * HF + tid];
    v = v > 0.f ? v : expm1f(v);
    __shared__ float sh[64];
    sh[tid] = v;
    __syncthreads();
    float o = mlp_b[g * HF + tid];
    const float* mw = mlp_W + (size_t)g * HF * HF + tid;
    #pragma unroll 8
    for (int k = 0; k < 64; k++) o += sh[k] * mw[k * 64];
    g_feat[(size_t)n * (GG * HF) + g * HF + tid] = o;
}

// ---------------- final head + log_softmax ----------------
__global__ void __launch_bounds__(128)
k_out(const float* __restrict__ out_W, const float* __restrict__ out_b,
      float* __restrict__ out)
{
    int node = blockIdx.x * 4 + (threadIdx.x >> 5);
    int lane = threadIdx.x & 31;
    float acc[CC];
    #pragma unroll
    for (int c = 0; c < CC; c++) acc[c] = 0.f;
    const float* fr = &g_feat[(size_t)node * (GG * HF)];
    for (int k = lane; k < GG * HF; k += 32) {
        float v = fr[k];
        v = v > 0.f ? v : expm1f(v);
        #pragma unroll
        for (int c = 0; c < CC; c++) acc[c] += v * out_W[k * CC + c];
    }
    #pragma unroll
    for (int c = 0; c < CC; c++) {
        #pragma unroll
        for (int o = 16; o; o >>= 1)
            acc[c] += __shfl_xor_sync(0xffffffffu, acc[c], o);
        acc[c] += out_b[c];
    }
    float m = acc[0];
    #pragma unroll
    for (int c = 1; c < CC; c++) m = fmaxf(m, acc[c]);
    float s = 0.f;
    #pragma unroll
    for (int c = 0; c < CC; c++) s += expf(acc[c] - m);
    float lse = m + logf(s);
    if (lane < CC) out[(size_t)node * CC + lane] = acc[lane] - lse;
}

// ---------------- launcher ----------------
extern "C" void kernel_launch(void* const* d_in, const int* in_sizes, int n_in,
                              void* d_out, int out_size)
{
    const float* x       = (const float*)d_in[0];
    const int*   ei      = (const int*)  d_in[1];
    const float* U       = (const float*)d_in[2];
    const float* psi     = (const float*)d_in[3];
    const float* gat_W   = (const float*)d_in[4];
    const float* att_src = (const float*)d_in[5];
    const float* att_dst = (const float*)d_in[6];
    const float* gat_b   = (const float*)d_in[7];
    const float* mlp_W   = (const float*)d_in[8];
    const float* mlp_b   = (const float*)d_in[9];
    const float* out_W   = (const float*)d_in[10];
    const float* out_b   = (const float*)d_in[11];
    float* out = (float*)d_out;

    constexpr int SM32 = 2 * (2 * 128 * 144 + 2 * 32 * 144);   // 92160
    constexpr int SM96 = 2 * (2 * 128 * 144 + 2 * 96 * 144);   // 129024
    cudaFuncSetAttribute((const void*)k_gemm_mma<32>,
                         cudaFuncAttributeMaxDynamicSharedMemorySize, SM32);
    cudaFuncSetAttribute((const void*)k_gemm_mma<96>,
                         cudaFuncAttributeMaxDynamicSharedMemorySize, SM96);

    // scattering-tree GEMM chain first (mma.sync, 3xBF16)
    k_absT<<<128, dim3(32, 8)>>>(x);
    k_gemm_mma<32><<<dim3(128, 1), 256, SM32>>>(U, psi, 1, 0, 32);   // [U;psi]@af
    k_a1T<<<dim3(128, 3), dim3(32, 8)>>>();
    k_gemm_mma<96><<<dim3(128, 1), 256, SM96>>>(U, psi, 1, 1, 96);   // [U;psi]@|y1|
    k_b3T<<<dim3(128, 9), dim3(32, 8)>>>();
    k_gemm_mma<96><<<dim3(32, 3), 256, SM96>>>(U, psi, 0, 2, 288);   // U@|y2|
    k_coefs<<<(GG * NN * FF) / 256, 256>>>();

    // CSR build (only needed before k_agg)
    k_csr_init<<<16, 256>>>();
    k_csr_hist<<<EE / 256, 256>>>(ei);
    k_csr_scan<<<1, 1024>>>();
    k_csr_scatter<<<ETOT / 256, 256>>>(ei);

    // GAT branches + MLPs
    k_h<<<dim3(NN / 16, GG), 64>>>(gat_W, att_src, att_dst);
    k_agg<<<dim3(NN, GG), 64>>>(gat_b, mlp_W, mlp_b);

    // final head + log_softmax
    k_out<<<NN / 4, 128>>>(out_W, out_b, out);
}